// round 10
// baseline (speedup 1.0000x reference)
#include <cuda_runtime.h>
#include <math.h>
#include <stddef.h>

// Problem dims
#define TT 512
#define BB 64
#define II 256
#define HH 512
#define OO 256
#define G4 (4*HH)
#define NBLK 128
// Grouped recurrence
#define NGRP 4
#define BPG  32          // blocks per group
#define BATG 16          // batches per group
#define COLB 16          // hidden cols per block (=> 64 gate rows per block)
#define NTHR 512         // threads per persist block (16 warps)

// ---------------- device scratch ----------------
__device__ float g_xp1[(size_t)TT*BB*G4];
__device__ float g_xp2[(size_t)BB*G4];
__device__ float g_hP[2][(size_t)BB*HH];    // ping-pong h, batch-major [b][col]
__device__ float g_hA[(size_t)BB*HH];       // layer-1 final h
__device__ float g_hs2[(size_t)TT*BB*HH];
__device__ unsigned g_flags[NBLK];          // zero-init; monotonic per-block step counters

// ---------------- helpers ----------------
typedef unsigned long long u64t;

__device__ __forceinline__ void fma2(u64t& acc, u64t a, u64t b) {
    asm volatile("fma.rn.f32x2 %0, %1, %2, %0;" : "+l"(acc) : "l"(a), "l"(b));
}
__device__ __forceinline__ u64t pk2(float x, float y) {
    u64t r; asm("mov.b64 %0, {%1, %2};" : "=l"(r) : "f"(x), "f"(y)); return r;
}
__device__ __forceinline__ float2 unpk2(u64t v) {
    float2 f; asm("mov.b64 {%0, %1}, %2;" : "=f"(f.x), "=f"(f.y) : "l"(v)); return f;
}
__device__ __forceinline__ void cp_async16(void* dst_smem, const void* src_gmem) {
    unsigned d = (unsigned)__cvta_generic_to_shared(dst_smem);
    asm volatile("cp.async.cg.shared.global [%0], [%1], 16;" :: "r"(d), "l"(src_gmem) : "memory");
}
__device__ __forceinline__ void st_release(unsigned* p, unsigned v) {
    asm volatile("st.global.release.gpu.u32 [%0], %1;" :: "l"(p), "r"(v) : "memory");
}
__device__ __forceinline__ unsigned ld_acquire(const unsigned* p) {
    unsigned r;
    asm volatile("ld.global.acquire.gpu.u32 %0, [%1];" : "=r"(r) : "l"(p) : "memory");
    return r;
}
__device__ __forceinline__ float fsig(float x)  { return __fdividef(1.f, 1.f + __expf(-x)); }
__device__ __forceinline__ float ftanh(float x) { return __fdividef(2.f, 1.f + __expf(-2.f*x)) - 1.f; }

// =================================================================================
// SGEMM with f32x2 (unchanged, passing)
// =================================================================================
__global__ __launch_bounds__(256) void gemm_bias_kernel(
    const float* __restrict__ A, const float* __restrict__ B,
    const float* __restrict__ bias1, const float* __restrict__ bias2,
    float* __restrict__ C, int M, int N, int K)
{
    __shared__ float As[8][128];
    __shared__ float Bs[8][128];

    const int tid  = threadIdx.x;
    const int row0 = blockIdx.y * 128;
    const int col0 = blockIdx.x * 128;

    const int lrow = tid >> 1;
    const int lcol = (tid & 1) << 2;
    const int tr   = (tid >> 4) << 3;
    const int tc   = (tid & 15) << 3;

    u64t acc2[4][8];
    #pragma unroll
    for (int i = 0; i < 4; i++)
        #pragma unroll
        for (int j = 0; j < 8; j++) acc2[i][j] = 0ull;

    for (int k0 = 0; k0 < K; k0 += 8) {
        float4 av = make_float4(0.f, 0.f, 0.f, 0.f);
        if (row0 + lrow < M)
            av = *(const float4*)(A + (size_t)(row0 + lrow) * K + k0 + lcol);
        As[lcol+0][lrow] = av.x;
        As[lcol+1][lrow] = av.y;
        As[lcol+2][lrow] = av.z;
        As[lcol+3][lrow] = av.w;

        float4 bv = *(const float4*)(B + (size_t)(col0 + lrow) * K + k0 + lcol);
        Bs[lcol+0][lrow] = bv.x;
        Bs[lcol+1][lrow] = bv.y;
        Bs[lcol+2][lrow] = bv.z;
        Bs[lcol+3][lrow] = bv.w;

        __syncthreads();

        #pragma unroll
        for (int kk = 0; kk < 8; kk++) {
            ulonglong2 raA = *(const ulonglong2*)&As[kk][tr];
            ulonglong2 raB = *(const ulonglong2*)&As[kk][tr + 4];
            float rb[8];
            *(float4*)(rb)     = *(const float4*)&Bs[kk][tc];
            *(float4*)(rb + 4) = *(const float4*)&Bs[kk][tc + 4];
            u64t rbd[8];
            #pragma unroll
            for (int j = 0; j < 8; j++) rbd[j] = pk2(rb[j], rb[j]);
            #pragma unroll
            for (int j = 0; j < 8; j++) {
                fma2(acc2[0][j], raA.x, rbd[j]);
                fma2(acc2[1][j], raA.y, rbd[j]);
                fma2(acc2[2][j], raB.x, rbd[j]);
                fma2(acc2[3][j], raB.y, rbd[j]);
            }
        }
        __syncthreads();
    }

    float bsum[8];
    #pragma unroll
    for (int j = 0; j < 8; j++) {
        float b = bias1 ? bias1[col0 + tc + j] : 0.f;
        if (bias2) b += bias2[col0 + tc + j];
        bsum[j] = b;
    }

    #pragma unroll
    for (int i2 = 0; i2 < 4; i2++) {
        #pragma unroll
        for (int half = 0; half < 2; half++) {
            int r = row0 + tr + i2 * 2 + half;
            if (r < M) {
                #pragma unroll
                for (int j = 0; j < 8; j += 4) {
                    float4 o;
                    float2 u0 = unpk2(acc2[i2][j+0]);
                    float2 u1 = unpk2(acc2[i2][j+1]);
                    float2 u2 = unpk2(acc2[i2][j+2]);
                    float2 u3 = unpk2(acc2[i2][j+3]);
                    o.x = (half ? u0.y : u0.x) + bsum[j+0];
                    o.y = (half ? u1.y : u1.x) + bsum[j+1];
                    o.z = (half ? u2.y : u2.x) + bsum[j+2];
                    o.w = (half ? u3.y : u3.x) + bsum[j+3];
                    *(float4*)(C + (size_t)r * N + col0 + tc + j) = o;
                }
            }
        }
    }
}

// =================================================================================
// Grouped persistent LSTM, 512 threads (16 warps) for latency hiding.
// 4 groups x 32 blocks; group owns batches [16g,16g+16), block owns cols
// [16ib,16ib+16) => 64 gate rows (r = col*4 + gate). W staged once (128KB).
//
// Warp w: ks = w>>1 (k-slice of 64 k), rh = w&1 (row half: rows rh*32..rh*32+31).
// Lane: rg = lane>>2 (row quad), bq = lane&3 (batch quad).
// Thread tile: 4 rows (= col jzw = rh*8+rg, gates 0..3) x 4 batches x 64 k,
// f32x2 packed over k. acc = 16 u64 -> fits 128 regs at 512 thr.
// Reduction over 8 k-slices in smem; tail = 1 cell/thread on tid<256.
// Group-local 32-wide flag barrier.
// =================================================================================
#define WS4   (64*128)                   // W float4 count (128KB)
#define HS4   (BATG*128)                 // h float4 count (32KB)
#define RED4N (8*16*16)                  // red float4 count: [ks][jz][cb] (32KB)
#define STEP_SMEM_BYTES ((WS4 + HS4 + RED4N) * 16)   // 196,608 B... = 192KB

__global__ __launch_bounds__(NTHR, 1) void lstm_persist_kernel(
    const float* __restrict__ h0, const float* __restrict__ c0,
    float* __restrict__ h_final,
    const float* __restrict__ W, const float* __restrict__ xp,
    long long xp_t_stride, float* __restrict__ hs_out)
{
    extern __shared__ float smem[];
    float4* wS4  = (float4*)smem;                       // [64 rows][128 k4] swizzled
    float4* hS4  = (float4*)smem + WS4;                 // [16 b][128 k4] swizzled
    float4* red4 = (float4*)smem + WS4 + HS4;           // [8 ks][16 jz][16 cb] swizzled

    const int tid   = threadIdx.x;
    const int lane  = tid & 31;
    const int w     = tid >> 5;          // warp 0..15
    const int ks    = w >> 1;            // k-slice 0..7 (64 k each)
    const int rh    = w & 1;             // row half
    const int rg    = lane >> 2;         // row quad 0..7
    const int bq    = lane & 3;          // batch quad 0..3
    const int group = blockIdx.x >> 5;
    const int ib    = blockIdx.x & 31;
    const int jj0   = ib * COLB;
    const int bq0   = group * BATG;

    const int jzw   = rh * 8 + rg;       // this thread's column (0..15)
    const int rbase = jzw * 4;           // rows rbase..rbase+3 (gates)

    // ---- stage W once: row r = col*4 + gate; swizzle k4 ^ ((r>>2)&7) ----
    for (int idx = tid; idx < WS4; idx += NTHR) {
        int r = idx >> 7, k4 = idx & 127;
        int col = r >> 2, g = r & 3;
        wS4[r * 128 + (k4 ^ (col & 7))] =
            ((const float4*)(W + (size_t)(g * HH + jj0 + col) * HH))[k4];
    }

    // ---- tail cell state (tid < 256): cb = tid>>4, jz = tid&15 ----
    const int cb = tid >> 4, jz = tid & 15;
    const int bglob = bq0 + cb;
    const int jglob = jj0 + jz;
    float creg = 0.f;
    if (tid < 256) creg = c0[(size_t)bglob * HH + jglob];

    unsigned base;
    {
        __shared__ unsigned sb;
        if (tid == 0) sb = g_flags[blockIdx.x];
        __syncthreads();
        base = sb;
    }

    const int k4beg = ks * 16;

    for (int t = 0; t < TT; t++) {
        // ---- xp prefetch (consumed in tail) ----
        float xi = 0.f, xf = 0.f, xg = 0.f, xo = 0.f;
        if (tid < 256) {
            const float* xt = xp + (size_t)(xp_t_stride * t) + (size_t)bglob * G4 + jglob;
            xi = xt[0*HH];
            xf = xt[1*HH];
            xg = xt[2*HH];
            xo = xt[3*HH];
        }

        // ---- wait for group's previous-step h ----
        if (t > 0) {
            unsigned target = base + (unsigned)t;
            if (tid < BPG) {
                const unsigned* fp = &g_flags[group * BPG + tid];
                while ((int)(ld_acquire(fp) - target) < 0) { }
            }
            __syncthreads();
        }

        // ---- stage group's h slice (32KB); swizzle k4 ^ (bq*2) with bq=(bl>>2)&3 ----
        const float* hsrc = (t == 0) ? h0 : g_hP[(t + 1) & 1];
        for (int idx = tid; idx < HS4; idx += NTHR) {
            int bl = idx >> 7, k4 = idx & 127;
            cp_async16(hS4 + bl * 128 + (k4 ^ (((bl >> 2) & 3) << 1)),
                       (const float4*)hsrc + (size_t)(bq0 + bl) * 128 + k4);
        }
        asm volatile("cp.async.commit_group;" ::: "memory");
        asm volatile("cp.async.wait_group 0;" ::: "memory");
        __syncthreads();

        // ---- compute: 4 rows x 4 batches x 64 k per thread ----
        u64t acc2[4][4];                  // [gate rr][batch i]
        #pragma unroll
        for (int rr = 0; rr < 4; rr++)
            #pragma unroll
            for (int i = 0; i < 4; i++) acc2[rr][i] = 0ull;

        #pragma unroll 8
        for (int it = 0; it < 16; it++) {
            int k4 = k4beg + it;
            ulonglong2 wv[4];
            #pragma unroll
            for (int rr = 0; rr < 4; rr++)
                wv[rr] = *(const ulonglong2*)(wS4 + (rbase + rr) * 128 + (k4 ^ (jzw & 7)));
            ulonglong2 hv[4];
            #pragma unroll
            for (int i = 0; i < 4; i++)
                hv[i] = *(const ulonglong2*)(hS4 + (bq * 4 + i) * 128 + (k4 ^ (bq << 1)));
            #pragma unroll
            for (int rr = 0; rr < 4; rr++)
                #pragma unroll
                for (int i = 0; i < 4; i++) {
                    fma2(acc2[rr][i], hv[i].x, wv[rr].x);
                    fma2(acc2[rr][i], hv[i].y, wv[rr].y);
                }
        }

        // ---- partials: red4[ks][jzw][cb ^ jzw] = float4 over gates ----
        #pragma unroll
        for (int i = 0; i < 4; i++) {
            int cbx = bq * 4 + i;
            float2 s0 = unpk2(acc2[0][i]);
            float2 s1 = unpk2(acc2[1][i]);
            float2 s2 = unpk2(acc2[2][i]);
            float2 s3 = unpk2(acc2[3][i]);
            red4[ks * 256 + jzw * 16 + (cbx ^ (jzw & 15))] =
                make_float4(s0.x+s0.y, s1.x+s1.y, s2.x+s2.y, s3.x+s3.y);
        }
        __syncthreads();

        // ---- tail: one (batch, col) cell per thread, tid < 256 ----
        if (tid < 256) {
            float4 s = make_float4(0.f, 0.f, 0.f, 0.f);
            #pragma unroll
            for (int k = 0; k < 8; k++) {
                float4 q = red4[k * 256 + jz * 16 + (cb ^ (jz & 15))];
                s.x += q.x; s.y += q.y; s.z += q.z; s.w += q.w;
            }
            float gi = fsig (s.x + xi);
            float gf = fsig (s.y + xf);
            float gg = ftanh(s.z + xg);
            float go = fsig (s.w + xo);
            float cn = gf * creg + gi * gg;
            creg = cn;
            float hn = go * ftanh(cn);

            if (t < TT - 1)
                g_hP[t & 1][(size_t)bglob * HH + jglob] = hn;
            else
                h_final[(size_t)bglob * HH + jglob] = hn;
            if (hs_out)
                hs_out[(size_t)t * BB * HH + (size_t)bglob * HH + jglob] = hn;
        }
        __syncthreads();     // block's h writes complete before release
        if (t < TT - 1 && tid == 0)
            st_release(&g_flags[blockIdx.x], base + (unsigned)t + 1u);
    }
}

// =================================================================================
// Host launch — 5 graph nodes
// =================================================================================
extern "C" void kernel_launch(void* const* d_in, const int* in_sizes, int n_in,
                              void* d_out, int out_size)
{
    (void)in_sizes; (void)n_in; (void)out_size;
    const float* inputs = (const float*)d_in[0];
    const float* W_ih1  = (const float*)d_in[1];
    const float* W_hh1  = (const float*)d_in[2];
    const float* b_ih1  = (const float*)d_in[3];
    const float* b_hh1  = (const float*)d_in[4];
    const float* W_ih2  = (const float*)d_in[5];
    const float* W_hh2  = (const float*)d_in[6];
    const float* b_ih2  = (const float*)d_in[7];
    const float* b_hh2  = (const float*)d_in[8];
    const float* W_lin  = (const float*)d_in[9];
    const float* b_lin  = (const float*)d_in[10];
    const float* h1_0   = (const float*)d_in[11];
    const float* c1_0   = (const float*)d_in[12];
    const float* h2_0   = (const float*)d_in[13];
    const float* c2_0   = (const float*)d_in[14];
    float* out = (float*)d_out;

    float *xp1, *xp2, *hA, *hs2;
    cudaGetSymbolAddress((void**)&xp1, g_xp1);
    cudaGetSymbolAddress((void**)&xp2, g_xp2);
    cudaGetSymbolAddress((void**)&hA,  g_hA);
    cudaGetSymbolAddress((void**)&hs2, g_hs2);

    cudaFuncSetAttribute(lstm_persist_kernel,
                         cudaFuncAttributeMaxDynamicSharedMemorySize,
                         STEP_SMEM_BYTES);

    // xp1 = inputs @ W_ih1^T + b_ih1 + b_hh1
    gemm_bias_kernel<<<dim3(G4/128, (TT*BB)/128), 256>>>(
        inputs, W_ih1, b_ih1, b_hh1, xp1, TT*BB, G4, II);

    // Layer 1: final h (batch-major) -> hA
    lstm_persist_kernel<<<NBLK, NTHR, STEP_SMEM_BYTES>>>(
        h1_0, c1_0, hA, W_hh1, xp1, (long long)BB * G4, nullptr);

    // xp2 = h1T @ W_ih2^T + b_ih2 + b_hh2
    gemm_bias_kernel<<<dim3(G4/128, 1), 256>>>(
        hA, W_ih2, b_ih2, b_hh2, xp2, BB, G4, HH);

    // Layer 2: hidden sequence streamed to hs2
    lstm_persist_kernel<<<NBLK, NTHR, STEP_SMEM_BYTES>>>(
        h2_0, c2_0, hA, W_hh2, xp2, 0LL, hs2);

    // out = hs2 @ W_lin^T + b_lin
    gemm_bias_kernel<<<dim3(OO/128, (TT*BB)/128), 256>>>(
        hs2, W_lin, b_lin, nullptr, out, TT*BB, OO, HH);
}